// round 9
// baseline (speedup 1.0000x reference)
#include <cuda_runtime.h>
#include <math.h>

#define NB 8
#define NH 16
#define ND 1024
#define NHD 64
#define NPAST 8192
#define NBH (NB*NH)                   // 128
#define KEYS_PER_WARP 32
#define WARPS_PB 8
#define KEYS_PB (KEYS_PER_WARP*WARPS_PB)  // 256 keys per block
#define NCHUNK (NPAST/KEYS_PB)            // 32 block-chunks per (b,h)
#define NITER (KEYS_PER_WARP/2)           // 16 iterations (2 keys each)
#define LN10000 9.210340371976184f

// Scratch (allocation-free: __device__ globals)
__device__ float g_qkv[3*NB*ND];            // q | k_new | v_new (bias applied)
__device__ float g_m[NBH*NCHUNK];
__device__ float g_l[NBH*NCHUNK];
__device__ float g_acc[NBH*NCHUNK*NHD];     // 1 MB
__device__ float g_ctx[NB*ND];
__device__ int   g_done;                    // reduce-phase completion counter

// ---------------------------------------------------------------------------
// Kernel A1: Q projection, block-per-row.  grid 1024, 256 thr.
// Block 0 also resets g_done for this replay (stream-ordered before the scan).
// ---------------------------------------------------------------------------
__global__ void proj_q_kernel(const float* __restrict__ x,
                              const float* __restrict__ Wq,
                              const float* __restrict__ bq) {
    if (blockIdx.x == 0 && threadIdx.x == 0) g_done = 0;

    const int row = blockIdx.x;
    const int warp = threadIdx.x >> 5, lane = threadIdx.x & 31;
    const int c4 = warp*32 + lane;

    const float4 w4 = ((const float4*)(Wq + (size_t)row * ND))[c4];
    const float4* x4p = (const float4*)x;

    float acc[NB];
#pragma unroll
    for (int b = 0; b < NB; ++b) {
        const float4 x4 = __ldg(x4p + b*(ND/4) + c4);
        acc[b] = w4.x*x4.x + w4.y*x4.y + w4.z*x4.z + w4.w*x4.w;
    }
#pragma unroll
    for (int b = 0; b < NB; ++b) {
#pragma unroll
        for (int o = 16; o; o >>= 1) acc[b] += __shfl_xor_sync(0xffffffffu, acc[b], o);
    }
    __shared__ float sm[8][NB+1];
    if (lane == 0) {
#pragma unroll
        for (int b = 0; b < NB; ++b) sm[warp][b] = acc[b];
    }
    __syncthreads();
    if (threadIdx.x < NB) {
        const int b = threadIdx.x;
        float v = sm[0][b];
#pragma unroll
        for (int w = 1; w < 8; ++w) v += sm[w][b];
        g_qkv[b*ND + row] = v + bq[row];
    }
}

// ---------------------------------------------------------------------------
// Kernel A2: K/V projection (runs on side stream under attn_partial).
// ---------------------------------------------------------------------------
__global__ void proj_kv_kernel(const float* __restrict__ x,
                               const float* __restrict__ Wk, const float* __restrict__ bk,
                               const float* __restrict__ Wv, const float* __restrict__ bv) {
    const int r = blockIdx.x;
    const int which = r >> 10;                      // 0=k 1=v
    const int row = r & 1023;
    const float* W    = which ? Wv : Wk;
    const float* bias = which ? bv : bk;

    const int warp = threadIdx.x >> 5, lane = threadIdx.x & 31;
    const int c4 = warp*32 + lane;

    const float4 w4 = ((const float4*)(W + (size_t)row * ND))[c4];
    const float4* x4p = (const float4*)x;

    float acc[NB];
#pragma unroll
    for (int b = 0; b < NB; ++b) {
        const float4 x4 = __ldg(x4p + b*(ND/4) + c4);
        acc[b] = w4.x*x4.x + w4.y*x4.y + w4.z*x4.z + w4.w*x4.w;
    }
#pragma unroll
    for (int b = 0; b < NB; ++b) {
#pragma unroll
        for (int o = 16; o; o >>= 1) acc[b] += __shfl_xor_sync(0xffffffffu, acc[b], o);
    }
    __shared__ float sm[8][NB+1];
    if (lane == 0) {
#pragma unroll
        for (int b = 0; b < NB; ++b) sm[warp][b] = acc[b];
    }
    __syncthreads();
    if (threadIdx.x < NB) {
        const int b = threadIdx.x;
        float v = sm[0][b];
#pragma unroll
        for (int w = 1; w < 8; ++w) v += sm[w][b];
        g_qkv[(1 + which)*NB*ND + b*ND + row] = v + bias[row];
    }
}

// ---------------------------------------------------------------------------
// Kernel B: flash-decoding partials, two-phase per warp chunk (unchanged, won).
// ---------------------------------------------------------------------------
__global__ void attn_partial(const float* __restrict__ past_k,
                             const float* __restrict__ past_v) {
    const int bh   = blockIdx.y;
    const int warp = threadIdx.x >> 5, lane = threadIdx.x & 31;
    const int b = bh >> 4, h = bh & 15;

    __shared__ float qs[NHD];
    __shared__ float sm_m[WARPS_PB], sm_l[WARPS_PB];
    __shared__ float sm_acc[WARPS_PB][NHD];

    if (threadIdx.x < 32) {
        const int i = threadIdx.x;                  // freq index 0..31
        const float inv = expf(-((float)(2*i) / (float)NHD) * LN10000);
        float sn, cs; sincosf((float)NPAST * inv, &sn, &cs);
        const float* gq = g_qkv + b*ND + h*NHD;
        const float q1 = gq[i], q2 = gq[i+32];
        qs[i]    = q1*cs - q2*sn;
        qs[i+32] = q2*cs + q1*sn;
    }
    __syncthreads();

    const int l16 = lane & 15;
    const float4 q4 = ((const float4*)qs)[l16];

    const int wchunk = blockIdx.x * WARPS_PB + warp;   // 0..255
    const size_t off = ((size_t)bh * NPAST + (size_t)wchunk * KEYS_PER_WARP) * NHD;
    const float4* kb = (const float4*)(past_k + off);
    const float4* vb = (const float4*)(past_v + off);

    // ---- Phase 1: scores.  16 fully independent K loads. ----
    float s[NITER];
#pragma unroll
    for (int j = 0; j < NITER; ++j) {
        const float4 k4 = __ldcs(kb + j*32 + lane);
        float t = q4.x*k4.x + q4.y*k4.y + q4.z*k4.z + q4.w*k4.w;
        t += __shfl_xor_sync(0xffffffffu, t, 1);
        t += __shfl_xor_sync(0xffffffffu, t, 2);
        t += __shfl_xor_sync(0xffffffffu, t, 4);
        t += __shfl_xor_sync(0xffffffffu, t, 8);
        s[j] = t * 0.125f;                          // 1/sqrt(64)
    }

    // ---- Softmax over this lane's 16 scores. ----
    float m = s[0];
#pragma unroll
    for (int j = 1; j < NITER; ++j) m = fmaxf(m, s[j]);
    float l = 0.f;
#pragma unroll
    for (int j = 0; j < NITER; ++j) { s[j] = __expf(s[j] - m); l += s[j]; }

    // ---- Phase 2: weighted V accumulation.  16 independent V loads. ----
    float4 acc0 = make_float4(0.f,0.f,0.f,0.f);
    float4 acc1 = make_float4(0.f,0.f,0.f,0.f);
#pragma unroll
    for (int j = 0; j < NITER; j += 2) {
        const float4 va = __ldcs(vb + j*32 + lane);
        const float4 vc = __ldcs(vb + (j+1)*32 + lane);
        acc0.x += s[j]*va.x;   acc0.y += s[j]*va.y;
        acc0.z += s[j]*va.z;   acc0.w += s[j]*va.w;
        acc1.x += s[j+1]*vc.x; acc1.y += s[j+1]*vc.y;
        acc1.z += s[j+1]*vc.z; acc1.w += s[j+1]*vc.w;
    }
    float4 acc;
    acc.x = acc0.x + acc1.x; acc.y = acc0.y + acc1.y;
    acc.z = acc0.z + acc1.z; acc.w = acc0.w + acc1.w;

    // ---- Merge the two half-warp streams. ----
    const float mo = __shfl_xor_sync(0xffffffffu, m, 16);
    const float lo = __shfl_xor_sync(0xffffffffu, l, 16);
    float4 ao;
    ao.x = __shfl_xor_sync(0xffffffffu, acc.x, 16);
    ao.y = __shfl_xor_sync(0xffffffffu, acc.y, 16);
    ao.z = __shfl_xor_sync(0xffffffffu, acc.z, 16);
    ao.w = __shfl_xor_sync(0xffffffffu, acc.w, 16);
    const float M  = fmaxf(m, mo);
    const float wa = __expf(m - M), wb = __expf(mo - M);
    float4 comb;
    comb.x = acc.x*wa + ao.x*wb;
    comb.y = acc.y*wa + ao.y*wb;
    comb.z = acc.z*wa + ao.z*wb;
    comb.w = acc.w*wa + ao.w*wb;
    const float L = l*wa + lo*wb;

    if (lane < 16) ((float4*)sm_acc[warp])[l16] = comb;
    if (lane == 0) { sm_m[warp] = M; sm_l[warp] = L; }
    __syncthreads();

    if (threadIdx.x < NHD) {
        const int d = threadIdx.x;
        float Mb = sm_m[0];
#pragma unroll
        for (int w = 1; w < WARPS_PB; ++w) Mb = fmaxf(Mb, sm_m[w]);
        float Lb = 0.f, a = 0.f;
#pragma unroll
        for (int w = 0; w < WARPS_PB; ++w) {
            const float wg = __expf(sm_m[w] - Mb);
            a  += sm_acc[w][d] * wg;
            Lb += sm_l[w] * wg;
        }
        const int idx = bh*NCHUNK + blockIdx.x;
        g_acc[idx*NHD + d] = a;
        if (d == 0) { g_m[idx] = Mb; g_l[idx] = Lb; }
    }
}

// ---------------------------------------------------------------------------
// Kernel C: FUSED reduce + output projection.  grid 512, 256 thr.
// Every block first issues its 2 Wo-row loads (hide DRAM latency under the
// reduce).  Blocks 0..127 reduce their (b,h): explicit 8-deep load prefetch,
// parallel M, fold new key, write ctx, fence, bump g_done.  All blocks spin
// until g_done==NBH, then finish the batch-amortized output GEMV.
// ---------------------------------------------------------------------------
__global__ void __launch_bounds__(256)
reduce_outproj_kernel(const float* __restrict__ Wo,
                      const float* __restrict__ bo,
                      float* __restrict__ out) {
    const int tid = threadIdx.x;
    const int r0 = blockIdx.x * 2, r1 = r0 + 1;

    // ---- Issue Wo loads immediately (resolve during the reduce phase). ----
    const float4 w0 = ((const float4*)(Wo + (size_t)r0 * ND))[tid];
    const float4 w1 = ((const float4*)(Wo + (size_t)r1 * ND))[tid];

    // ---- Phase 1: blocks 0..127 reduce one (b,h). ----
    if (blockIdx.x < NBH) {
        const int bh = blockIdx.x;
        const int c = tid >> 6, d = tid & 63;       // c: 0..3
        const int b = bh >> 4, h = bh & 15;

        __shared__ float qs[NHD], ks[NHD];
        __shared__ float s_acc[4][NHD];
        __shared__ float s_l[4];
        __shared__ float sM, s_dot;

        const float* mptr = g_m + bh*NCHUNK;
        const float* lptr = g_l + bh*NCHUNK;
        const float* aptr = g_acc + (size_t)bh*NCHUNK*NHD;

        if (tid < 32) {                             // parallel max over 32 chunks
            float mv = mptr[tid];
#pragma unroll
            for (int o = 16; o; o >>= 1) mv = fmaxf(mv, __shfl_xor_sync(0xffffffffu, mv, o));
            if (tid == 0) sM = mv;
        } else if (tid < 64) {                      // RoPE q & k_new (lanes 32..63 -> i 0..31)
            const int i = tid - 32;
            const float inv = expf(-((float)(2*i) / (float)NHD) * LN10000);
            float sn, cs; sincosf((float)NPAST * inv, &sn, &cs);
            const float* gq = g_qkv + b*ND + h*NHD;
            const float* gk = g_qkv + NB*ND + b*ND + h*NHD;
            const float q1 = gq[i], q2 = gq[i+32];
            qs[i]    = q1*cs - q2*sn;
            qs[i+32] = q2*cs + q1*sn;
            const float k1 = gk[i], k2 = gk[i+32];
            ks[i]    = k1*cs - k2*sn;
            ks[i+32] = k2*cs + k1*sn;
        }
        __syncthreads();
        const float M = sM;

        // Explicit prefetch: 8 independent acc/m/l loads batched up front.
        float av[8], mv8[8], lv8[8];
#pragma unroll
        for (int j = 0; j < 8; ++j) {
            const int i = c + 4*j;
            av[j]  = aptr[i*NHD + d];
            mv8[j] = mptr[i];
            lv8[j] = lptr[i];
        }
        float a = 0.f, L = 0.f;
#pragma unroll
        for (int j = 0; j < 8; ++j) {
            const float w = __expf(mv8[j] - M);
            a += av[j] * w;
            L += lv8[j] * w;
        }
        s_acc[c][d] = a;
        if (d == 0) s_l[c] = L;

        // New-key score: q · k_new (warp 0 after qs/ks ready).
        __syncthreads();
        if (tid < 32) {
            float v = qs[tid]*ks[tid] + qs[tid+32]*ks[tid+32];
#pragma unroll
            for (int o = 16; o; o >>= 1) v += __shfl_xor_sync(0xffffffffu, v, o);
            if (tid == 0) s_dot = v * 0.125f;
        }
        __syncthreads();

        if (tid < NHD) {
            const int d2 = tid;
            float A  = s_acc[0][d2] + s_acc[1][d2] + s_acc[2][d2] + s_acc[3][d2];
            float Lt = s_l[0] + s_l[1] + s_l[2] + s_l[3];
            const float s_new = s_dot;
            const float M2 = fmaxf(M, s_new);
            const float w0_ = __expf(M - M2);
            const float p   = __expf(s_new - M2);
            const float vd  = g_qkv[2*NB*ND + b*ND + h*NHD + d2];
            A  = A*w0_ + p*vd;
            Lt = Lt*w0_ + p;
            g_ctx[b*ND + h*NHD + d2] = A / Lt;
        }
        __threadfence();
        __syncthreads();
        if (tid == 0) atomicAdd(&g_done, 1);
    }

    // ---- Spin until all 128 ctx tiles are published. ----
    if (tid == 0) {
        while (*(volatile int*)&g_done < NBH) { }
    }
    __syncthreads();
    __threadfence();

    // ---- Phase 2: output GEMV, 2 rows per block, 8 batches. ----
    const float4* cp = (const float4*)g_ctx;
    float a0[NB], a1[NB];
#pragma unroll
    for (int b = 0; b < NB; ++b) {
        const float4 cv = cp[b*(ND/4) + tid];
        a0[b] = w0.x*cv.x + w0.y*cv.y + w0.z*cv.z + w0.w*cv.w;
        a1[b] = w1.x*cv.x + w1.y*cv.y + w1.z*cv.z + w1.w*cv.w;
    }
#pragma unroll
    for (int b = 0; b < NB; ++b) {
#pragma unroll
        for (int o = 16; o; o >>= 1) {
            a0[b] += __shfl_xor_sync(0xffffffffu, a0[b], o);
            a1[b] += __shfl_xor_sync(0xffffffffu, a1[b], o);
        }
    }
    __shared__ float smo[8][2][NB];
    const int warp = tid >> 5, lane = tid & 31;
    if (lane == 0) {
#pragma unroll
        for (int b = 0; b < NB; ++b) { smo[warp][0][b] = a0[b]; smo[warp][1][b] = a1[b]; }
    }
    __syncthreads();
    if (tid < 2*NB) {
        const int rr = tid >> 3, b = tid & 7;       // rr: 0/1, b: 0..7
        float v = smo[0][rr][b];
#pragma unroll
        for (int w = 1; w < 8; ++w) v += smo[w][rr][b];
        const int row = rr ? r1 : r0;
        out[b*ND + row] = v + bo[row];
    }
}

// ---------------------------------------------------------------------------
extern "C" void kernel_launch(void* const* d_in, const int* in_sizes, int n_in,
                              void* d_out, int out_size) {
    const float* x      = (const float*)d_in[0];
    const float* Wq     = (const float*)d_in[1];
    const float* bq     = (const float*)d_in[2];
    const float* Wk     = (const float*)d_in[3];
    const float* bk     = (const float*)d_in[4];
    const float* Wv     = (const float*)d_in[5];
    const float* bv     = (const float*)d_in[6];
    const float* Wo     = (const float*)d_in[7];
    const float* bo     = (const float*)d_in[8];
    const float* past_k = (const float*)d_in[9];
    const float* past_v = (const float*)d_in[10];
    float* out = (float*)d_out;

    static cudaStream_t s_side = nullptr;
    static cudaEvent_t  e_fork = nullptr, e_join = nullptr;
    if (s_side == nullptr) {
        cudaStreamCreateWithFlags(&s_side, cudaStreamNonBlocking);
        cudaEventCreateWithFlags(&e_fork, cudaEventDisableTiming);
        cudaEventCreateWithFlags(&e_join, cudaEventDisableTiming);
    }

    cudaEventRecord(e_fork, 0);
    cudaStreamWaitEvent(s_side, e_fork, 0);

    proj_q_kernel<<<ND, 256>>>(x, Wq, bq);                          // main (+g_done reset)
    proj_kv_kernel<<<2*ND, 256, 0, s_side>>>(x, Wk, bk, Wv, bv);    // side
    attn_partial<<<dim3(NCHUNK, NBH), 256>>>(past_k, past_v);       // main

    cudaEventRecord(e_join, s_side);
    cudaStreamWaitEvent(0, e_join, 0);

    reduce_outproj_kernel<<<ND/2, 256>>>(Wo, bo, out);
}

// round 10
// speedup vs baseline: 1.0217x; 1.0217x over previous
#include <cuda_runtime.h>
#include <math.h>

#define NB 8
#define NH 16
#define ND 1024
#define NHD 64
#define NPAST 8192
#define NBH (NB*NH)                   // 128
#define KEYS_PER_WARP 32
#define WARPS_PB 8
#define KEYS_PB (KEYS_PER_WARP*WARPS_PB)  // 256 keys per block
#define NCHUNK (NPAST/KEYS_PB)            // 32 block-chunks per (b,h)
#define NITER (KEYS_PER_WARP/2)           // 16 iterations (2 keys each)
#define LN10000 9.210340371976184f

// Scratch (allocation-free: __device__ globals)
__device__ float g_qkv[3*NB*ND];            // q | k_new | v_new (bias applied)
__device__ float g_m[NBH*NCHUNK];
__device__ float g_l[NBH*NCHUNK];
__device__ float g_acc[NBH*NCHUNK*NHD];     // 1 MB
__device__ float g_ctx[NB*ND];
__device__ int   g_cnt[NBH];                // per-(b,h) chunk completion counters

// ---------------------------------------------------------------------------
// Kernel A1: Q projection, block-per-row.  grid 1024, 256 thr.
// Also resets the per-bh counters for this replay (stream/event-ordered
// before both attn_partial and reduce_spin).
// ---------------------------------------------------------------------------
__global__ void proj_q_kernel(const float* __restrict__ x,
                              const float* __restrict__ Wq,
                              const float* __restrict__ bq) {
    if (blockIdx.x < NBH && threadIdx.x == 0) g_cnt[blockIdx.x] = 0;

    const int row = blockIdx.x;
    const int warp = threadIdx.x >> 5, lane = threadIdx.x & 31;
    const int c4 = warp*32 + lane;

    const float4 w4 = ((const float4*)(Wq + (size_t)row * ND))[c4];
    const float4* x4p = (const float4*)x;

    float acc[NB];
#pragma unroll
    for (int b = 0; b < NB; ++b) {
        const float4 x4 = __ldg(x4p + b*(ND/4) + c4);
        acc[b] = w4.x*x4.x + w4.y*x4.y + w4.z*x4.z + w4.w*x4.w;
    }
#pragma unroll
    for (int b = 0; b < NB; ++b) {
#pragma unroll
        for (int o = 16; o; o >>= 1) acc[b] += __shfl_xor_sync(0xffffffffu, acc[b], o);
    }
    __shared__ float sm[8][NB+1];
    if (lane == 0) {
#pragma unroll
        for (int b = 0; b < NB; ++b) sm[warp][b] = acc[b];
    }
    __syncthreads();
    if (threadIdx.x < NB) {
        const int b = threadIdx.x;
        float v = sm[0][b];
#pragma unroll
        for (int w = 1; w < 8; ++w) v += sm[w][b];
        g_qkv[b*ND + row] = v + bq[row];
    }
}

// ---------------------------------------------------------------------------
// Kernel A2: K/V projection (side stream, overlapped with the scan).
// ---------------------------------------------------------------------------
__global__ void proj_kv_kernel(const float* __restrict__ x,
                               const float* __restrict__ Wk, const float* __restrict__ bk,
                               const float* __restrict__ Wv, const float* __restrict__ bv) {
    const int r = blockIdx.x;
    const int which = r >> 10;                      // 0=k 1=v
    const int row = r & 1023;
    const float* W    = which ? Wv : Wk;
    const float* bias = which ? bv : bk;

    const int warp = threadIdx.x >> 5, lane = threadIdx.x & 31;
    const int c4 = warp*32 + lane;

    const float4 w4 = ((const float4*)(W + (size_t)row * ND))[c4];
    const float4* x4p = (const float4*)x;

    float acc[NB];
#pragma unroll
    for (int b = 0; b < NB; ++b) {
        const float4 x4 = __ldg(x4p + b*(ND/4) + c4);
        acc[b] = w4.x*x4.x + w4.y*x4.y + w4.z*x4.z + w4.w*x4.w;
    }
#pragma unroll
    for (int b = 0; b < NB; ++b) {
#pragma unroll
        for (int o = 16; o; o >>= 1) acc[b] += __shfl_xor_sync(0xffffffffu, acc[b], o);
    }
    __shared__ float sm[8][NB+1];
    if (lane == 0) {
#pragma unroll
        for (int b = 0; b < NB; ++b) sm[warp][b] = acc[b];
    }
    __syncthreads();
    if (threadIdx.x < NB) {
        const int b = threadIdx.x;
        float v = sm[0][b];
#pragma unroll
        for (int w = 1; w < 8; ++w) v += sm[w][b];
        g_qkv[(1 + which)*NB*ND + b*ND + row] = v + bias[row];
    }
}

// ---------------------------------------------------------------------------
// Kernel B: flash-decoding partials, two-phase per warp chunk.
// After publishing its partial, each block release-bumps g_cnt[bh] so the
// side-stream reducer can consume this (b,h) while the scan continues.
// ---------------------------------------------------------------------------
__global__ void __launch_bounds__(256, 6)
attn_partial(const float* __restrict__ past_k,
             const float* __restrict__ past_v) {
    const int bh   = blockIdx.y;
    const int warp = threadIdx.x >> 5, lane = threadIdx.x & 31;
    const int b = bh >> 4, h = bh & 15;

    __shared__ float qs[NHD];
    __shared__ float sm_m[WARPS_PB], sm_l[WARPS_PB];
    __shared__ float sm_acc[WARPS_PB][NHD];

    if (threadIdx.x < 32) {
        const int i = threadIdx.x;                  // freq index 0..31
        const float inv = expf(-((float)(2*i) / (float)NHD) * LN10000);
        float sn, cs; sincosf((float)NPAST * inv, &sn, &cs);
        const float* gq = g_qkv + b*ND + h*NHD;
        const float q1 = gq[i], q2 = gq[i+32];
        qs[i]    = q1*cs - q2*sn;
        qs[i+32] = q2*cs + q1*sn;
    }
    __syncthreads();

    const int l16 = lane & 15;
    const float4 q4 = ((const float4*)qs)[l16];

    const int wchunk = blockIdx.x * WARPS_PB + warp;   // 0..255
    const size_t off = ((size_t)bh * NPAST + (size_t)wchunk * KEYS_PER_WARP) * NHD;
    const float4* kb = (const float4*)(past_k + off);
    const float4* vb = (const float4*)(past_v + off);

    // ---- Phase 1: scores.  16 fully independent K loads. ----
    float s[NITER];
#pragma unroll
    for (int j = 0; j < NITER; ++j) {
        const float4 k4 = __ldcs(kb + j*32 + lane);
        float t = q4.x*k4.x + q4.y*k4.y + q4.z*k4.z + q4.w*k4.w;
        t += __shfl_xor_sync(0xffffffffu, t, 1);
        t += __shfl_xor_sync(0xffffffffu, t, 2);
        t += __shfl_xor_sync(0xffffffffu, t, 4);
        t += __shfl_xor_sync(0xffffffffu, t, 8);
        s[j] = t * 0.125f;                          // 1/sqrt(64)
    }

    // ---- Softmax over this lane's 16 scores. ----
    float m = s[0];
#pragma unroll
    for (int j = 1; j < NITER; ++j) m = fmaxf(m, s[j]);
    float l = 0.f;
#pragma unroll
    for (int j = 0; j < NITER; ++j) { s[j] = __expf(s[j] - m); l += s[j]; }

    // ---- Phase 2: weighted V accumulation.  16 independent V loads. ----
    float4 acc0 = make_float4(0.f,0.f,0.f,0.f);
    float4 acc1 = make_float4(0.f,0.f,0.f,0.f);
#pragma unroll
    for (int j = 0; j < NITER; j += 2) {
        const float4 va = __ldcs(vb + j*32 + lane);
        const float4 vc = __ldcs(vb + (j+1)*32 + lane);
        acc0.x += s[j]*va.x;   acc0.y += s[j]*va.y;
        acc0.z += s[j]*va.z;   acc0.w += s[j]*va.w;
        acc1.x += s[j+1]*vc.x; acc1.y += s[j+1]*vc.y;
        acc1.z += s[j+1]*vc.z; acc1.w += s[j+1]*vc.w;
    }
    float4 acc;
    acc.x = acc0.x + acc1.x; acc.y = acc0.y + acc1.y;
    acc.z = acc0.z + acc1.z; acc.w = acc0.w + acc1.w;

    // ---- Merge the two half-warp streams. ----
    const float mo = __shfl_xor_sync(0xffffffffu, m, 16);
    const float lo = __shfl_xor_sync(0xffffffffu, l, 16);
    float4 ao;
    ao.x = __shfl_xor_sync(0xffffffffu, acc.x, 16);
    ao.y = __shfl_xor_sync(0xffffffffu, acc.y, 16);
    ao.z = __shfl_xor_sync(0xffffffffu, acc.z, 16);
    ao.w = __shfl_xor_sync(0xffffffffu, acc.w, 16);
    const float M  = fmaxf(m, mo);
    const float wa = __expf(m - M), wb = __expf(mo - M);
    float4 comb;
    comb.x = acc.x*wa + ao.x*wb;
    comb.y = acc.y*wa + ao.y*wb;
    comb.z = acc.z*wa + ao.z*wb;
    comb.w = acc.w*wa + ao.w*wb;
    const float L = l*wa + lo*wb;

    if (lane < 16) ((float4*)sm_acc[warp])[l16] = comb;
    if (lane == 0) { sm_m[warp] = M; sm_l[warp] = L; }
    __syncthreads();

    if (threadIdx.x < NHD) {
        const int d = threadIdx.x;
        float Mb = sm_m[0];
#pragma unroll
        for (int w = 1; w < WARPS_PB; ++w) Mb = fmaxf(Mb, sm_m[w]);
        float Lb = 0.f, a = 0.f;
#pragma unroll
        for (int w = 0; w < WARPS_PB; ++w) {
            const float wg = __expf(sm_m[w] - Mb);
            a  += sm_acc[w][d] * wg;
            Lb += sm_l[w] * wg;
        }
        const int idx = bh*NCHUNK + blockIdx.x;
        g_acc[idx*NHD + d] = a;
        if (d == 0) { g_m[idx] = Mb; g_l[idx] = Lb; }
    }

    // ---- Release: publish this chunk to the side-stream reducer. ----
    __threadfence();
    __syncthreads();
    if (threadIdx.x == 0) atomicAdd(&g_cnt[bh], 1);
}

// ---------------------------------------------------------------------------
// Kernel C (side stream): per-bh reduce, overlapped with the scan.
// grid NBH, 256 thr.  Spins until its (b,h)'s 32 chunks are published, then
// combines them + folds in the new key/value (RoPE fused), writes ctx.
// Tiny footprint (128 blocks) -> negligible residency theft from the scan.
// ---------------------------------------------------------------------------
__global__ void __launch_bounds__(256)
reduce_spin_kernel() {
    const int bh  = blockIdx.x;
    const int tid = threadIdx.x;
    const int c = tid >> 6, d = tid & 63;
    const int b = bh >> 4, h = bh & 15;

    __shared__ float qs[NHD], ks[NHD];
    __shared__ float s_acc[4][NHD];
    __shared__ float s_l[4];
    __shared__ float s_dot;

    // RoPE q & k_new while waiting (independent of the scan's partials).
    if (tid < 32) {
        const int i = tid;
        const float inv = expf(-((float)(2*i) / (float)NHD) * LN10000);
        float sn, cs; sincosf((float)NPAST * inv, &sn, &cs);
        const float* gq = g_qkv + b*ND + h*NHD;
        const float* gk = g_qkv + NB*ND + b*ND + h*NHD;
        const float q1 = gq[i], q2 = gq[i+32];
        qs[i]    = q1*cs - q2*sn;
        qs[i+32] = q2*cs + q1*sn;
        const float k1 = gk[i], k2 = gk[i+32];
        ks[i]    = k1*cs - k2*sn;
        ks[i+32] = k2*cs + k1*sn;
    }
    __syncthreads();

    if (tid < 32) {
        float v = qs[tid]*ks[tid] + qs[tid+32]*ks[tid+32];
#pragma unroll
        for (int o = 16; o; o >>= 1) v += __shfl_xor_sync(0xffffffffu, v, o);
        if (tid == 0) s_dot = v * 0.125f;
    }

    // Acquire: wait for all 32 chunks of this (b,h).
    if (tid == 0) {
        while (atomicAdd(&g_cnt[bh], 0) < NCHUNK) __nanosleep(128);
    }
    __syncthreads();
    __threadfence();

    const float* mptr = g_m + bh*NCHUNK;
    const float* lptr = g_l + bh*NCHUNK;
    const float* aptr = g_acc + (size_t)bh*NCHUNK*NHD;

    float M = -1e30f;
#pragma unroll
    for (int i = 0; i < NCHUNK; ++i) M = fmaxf(M, mptr[i]);

    // Explicit prefetch: 8 independent acc/m/l loads batched up front.
    float av[8], mv8[8], lv8[8];
#pragma unroll
    for (int j = 0; j < 8; ++j) {
        const int i = c + 4*j;
        av[j]  = aptr[i*NHD + d];
        mv8[j] = mptr[i];
        lv8[j] = lptr[i];
    }
    float a = 0.f, L = 0.f;
#pragma unroll
    for (int j = 0; j < 8; ++j) {
        const float w = __expf(mv8[j] - M);
        a += av[j] * w;
        L += lv8[j] * w;
    }
    s_acc[c][d] = a;
    if (d == 0) s_l[c] = L;
    __syncthreads();

    if (tid < NHD) {
        float A  = s_acc[0][tid] + s_acc[1][tid] + s_acc[2][tid] + s_acc[3][tid];
        float Lt = s_l[0] + s_l[1] + s_l[2] + s_l[3];
        const float s_new = s_dot;
        const float M2 = fmaxf(M, s_new);
        const float w0 = __expf(M - M2);
        const float p  = __expf(s_new - M2);
        const float vd = g_qkv[2*NB*ND + b*ND + h*NHD + tid];
        A  = A*w0 + p*vd;
        Lt = Lt*w0 + p;
        g_ctx[b*ND + h*NHD + tid] = A / Lt;
    }
}

// ---------------------------------------------------------------------------
// Kernel D: output projection.  grid 512, 256 thr, 2 rows per block.
// Wo loads issued first; ctx is L2-hot from the just-finished reduce.
// ---------------------------------------------------------------------------
__global__ void __launch_bounds__(256)
outproj_kernel(const float* __restrict__ Wo,
               const float* __restrict__ bo,
               float* __restrict__ out) {
    const int tid = threadIdx.x;
    const int r0 = blockIdx.x * 2, r1 = r0 + 1;

    const float4 w0 = ((const float4*)(Wo + (size_t)r0 * ND))[tid];
    const float4 w1 = ((const float4*)(Wo + (size_t)r1 * ND))[tid];

    const float4* cp = (const float4*)g_ctx;
    float a0[NB], a1[NB];
#pragma unroll
    for (int b = 0; b < NB; ++b) {
        const float4 cv = cp[b*(ND/4) + tid];
        a0[b] = w0.x*cv.x + w0.y*cv.y + w0.z*cv.z + w0.w*cv.w;
        a1[b] = w1.x*cv.x + w1.y*cv.y + w1.z*cv.z + w1.w*cv.w;
    }
#pragma unroll
    for (int b = 0; b < NB; ++b) {
#pragma unroll
        for (int o = 16; o; o >>= 1) {
            a0[b] += __shfl_xor_sync(0xffffffffu, a0[b], o);
            a1[b] += __shfl_xor_sync(0xffffffffu, a1[b], o);
        }
    }
    __shared__ float smo[8][2][NB];
    const int warp = tid >> 5, lane = tid & 31;
    if (lane == 0) {
#pragma unroll
        for (int b = 0; b < NB; ++b) { smo[warp][0][b] = a0[b]; smo[warp][1][b] = a1[b]; }
    }
    __syncthreads();
    if (tid < 2*NB) {
        const int rr = tid >> 3, b = tid & 7;
        float v = smo[0][rr][b];
#pragma unroll
        for (int w = 1; w < 8; ++w) v += smo[w][rr][b];
        const int row = rr ? r1 : r0;
        out[b*ND + row] = v + bo[row];
    }
}

// ---------------------------------------------------------------------------
extern "C" void kernel_launch(void* const* d_in, const int* in_sizes, int n_in,
                              void* d_out, int out_size) {
    const float* x      = (const float*)d_in[0];
    const float* Wq     = (const float*)d_in[1];
    const float* bq     = (const float*)d_in[2];
    const float* Wk     = (const float*)d_in[3];
    const float* bk     = (const float*)d_in[4];
    const float* Wv     = (const float*)d_in[5];
    const float* bv     = (const float*)d_in[6];
    const float* Wo     = (const float*)d_in[7];
    const float* bo     = (const float*)d_in[8];
    const float* past_k = (const float*)d_in[9];
    const float* past_v = (const float*)d_in[10];
    float* out = (float*)d_out;

    static cudaStream_t s_side = nullptr;
    static cudaEvent_t  e_fork = nullptr, e_join = nullptr;
    if (s_side == nullptr) {
        cudaStreamCreateWithFlags(&s_side, cudaStreamNonBlocking);
        cudaEventCreateWithFlags(&e_fork, cudaEventDisableTiming);
        cudaEventCreateWithFlags(&e_join, cudaEventDisableTiming);
    }

    // proj_q also resets g_cnt; fork AFTER it so both streams see the reset.
    proj_q_kernel<<<ND, 256>>>(x, Wq, bq);
    cudaEventRecord(e_fork, 0);
    cudaStreamWaitEvent(s_side, e_fork, 0);

    attn_partial<<<dim3(NCHUNK, NBH), 256>>>(past_k, past_v);       // main
    proj_kv_kernel<<<2*ND, 256, 0, s_side>>>(x, Wk, bk, Wv, bv);    // side
    reduce_spin_kernel<<<NBH, 256, 0, s_side>>>();                  // side (overlapped)

    cudaEventRecord(e_join, s_side);
    cudaStreamWaitEvent(0, e_join, 0);

    outproj_kernel<<<ND/2, 256>>>(Wo, bo, out);
}

// round 11
// speedup vs baseline: 1.0397x; 1.0176x over previous
#include <cuda_runtime.h>
#include <math.h>

#define NB 8
#define NH 16
#define ND 1024
#define NHD 64
#define NPAST 8192
#define NBH (NB*NH)                   // 128
#define KEYS_PER_WARP 32
#define WARPS_PB 8
#define KEYS_PB (KEYS_PER_WARP*WARPS_PB)  // 256 keys per block
#define NCHUNK (NPAST/KEYS_PB)            // 32 block-chunks per (b,h)
#define NITER (KEYS_PER_WARP/2)           // 16 iterations (2 keys each)
#define ROWS_PB (ND/NBH)                  // 8 output rows per reducer block
#define LN10000 9.210340371976184f

// Scratch (allocation-free: __device__ globals)
__device__ float g_qkv[3*NB*ND];            // q | k_new | v_new (bias applied)
__device__ float g_m[NBH*NCHUNK];
__device__ float g_l[NBH*NCHUNK];
__device__ float g_acc[NBH*NCHUNK*NHD];     // 1 MB
__device__ float g_ctx[NB*ND];
__device__ int   g_cnt[NBH];                // per-(b,h) chunk completion counters
__device__ int   g_ctxdone;                 // ctx completion counter

// ---------------------------------------------------------------------------
// Kernel A1: Q projection, block-per-row.  grid 1024, 256 thr.
// Also resets the sync counters for this replay (ordered before both streams'
// consumers via the fork event recorded after this kernel).
// ---------------------------------------------------------------------------
__global__ void proj_q_kernel(const float* __restrict__ x,
                              const float* __restrict__ Wq,
                              const float* __restrict__ bq) {
    if (threadIdx.x == 0) {
        if (blockIdx.x < NBH) g_cnt[blockIdx.x] = 0;
        if (blockIdx.x == 0)  g_ctxdone = 0;
    }

    const int row = blockIdx.x;
    const int warp = threadIdx.x >> 5, lane = threadIdx.x & 31;
    const int c4 = warp*32 + lane;

    const float4 w4 = ((const float4*)(Wq + (size_t)row * ND))[c4];
    const float4* x4p = (const float4*)x;

    float acc[NB];
#pragma unroll
    for (int b = 0; b < NB; ++b) {
        const float4 x4 = __ldg(x4p + b*(ND/4) + c4);
        acc[b] = w4.x*x4.x + w4.y*x4.y + w4.z*x4.z + w4.w*x4.w;
    }
#pragma unroll
    for (int b = 0; b < NB; ++b) {
#pragma unroll
        for (int o = 16; o; o >>= 1) acc[b] += __shfl_xor_sync(0xffffffffu, acc[b], o);
    }
    __shared__ float sm[8][NB+1];
    if (lane == 0) {
#pragma unroll
        for (int b = 0; b < NB; ++b) sm[warp][b] = acc[b];
    }
    __syncthreads();
    if (threadIdx.x < NB) {
        const int b = threadIdx.x;
        float v = sm[0][b];
#pragma unroll
        for (int w = 1; w < 8; ++w) v += sm[w][b];
        g_qkv[b*ND + row] = v + bq[row];
    }
}

// ---------------------------------------------------------------------------
// Kernel A2: K/V projection (side stream, overlapped with the scan).
// ---------------------------------------------------------------------------
__global__ void proj_kv_kernel(const float* __restrict__ x,
                               const float* __restrict__ Wk, const float* __restrict__ bk,
                               const float* __restrict__ Wv, const float* __restrict__ bv) {
    const int r = blockIdx.x;
    const int which = r >> 10;                      // 0=k 1=v
    const int row = r & 1023;
    const float* W    = which ? Wv : Wk;
    const float* bias = which ? bv : bk;

    const int warp = threadIdx.x >> 5, lane = threadIdx.x & 31;
    const int c4 = warp*32 + lane;

    const float4 w4 = ((const float4*)(W + (size_t)row * ND))[c4];
    const float4* x4p = (const float4*)x;

    float acc[NB];
#pragma unroll
    for (int b = 0; b < NB; ++b) {
        const float4 x4 = __ldg(x4p + b*(ND/4) + c4);
        acc[b] = w4.x*x4.x + w4.y*x4.y + w4.z*x4.z + w4.w*x4.w;
    }
#pragma unroll
    for (int b = 0; b < NB; ++b) {
#pragma unroll
        for (int o = 16; o; o >>= 1) acc[b] += __shfl_xor_sync(0xffffffffu, acc[b], o);
    }
    __shared__ float sm[8][NB+1];
    if (lane == 0) {
#pragma unroll
        for (int b = 0; b < NB; ++b) sm[warp][b] = acc[b];
    }
    __syncthreads();
    if (threadIdx.x < NB) {
        const int b = threadIdx.x;
        float v = sm[0][b];
#pragma unroll
        for (int w = 1; w < 8; ++w) v += sm[w][b];
        g_qkv[(1 + which)*NB*ND + b*ND + row] = v + bias[row];
    }
}

// ---------------------------------------------------------------------------
// Kernel B: flash-decoding partials, two-phase per warp chunk (unchanged).
// Release-bumps g_cnt[bh] so the overlapped reducer can consume this (b,h).
// ---------------------------------------------------------------------------
__global__ void __launch_bounds__(256, 6)
attn_partial(const float* __restrict__ past_k,
             const float* __restrict__ past_v) {
    const int bh   = blockIdx.y;
    const int warp = threadIdx.x >> 5, lane = threadIdx.x & 31;
    const int b = bh >> 4, h = bh & 15;

    __shared__ float qs[NHD];
    __shared__ float sm_m[WARPS_PB], sm_l[WARPS_PB];
    __shared__ float sm_acc[WARPS_PB][NHD];

    if (threadIdx.x < 32) {
        const int i = threadIdx.x;                  // freq index 0..31
        const float inv = expf(-((float)(2*i) / (float)NHD) * LN10000);
        float sn, cs; sincosf((float)NPAST * inv, &sn, &cs);
        const float* gq = g_qkv + b*ND + h*NHD;
        const float q1 = gq[i], q2 = gq[i+32];
        qs[i]    = q1*cs - q2*sn;
        qs[i+32] = q2*cs + q1*sn;
    }
    __syncthreads();

    const int l16 = lane & 15;
    const float4 q4 = ((const float4*)qs)[l16];

    const int wchunk = blockIdx.x * WARPS_PB + warp;   // 0..255
    const size_t off = ((size_t)bh * NPAST + (size_t)wchunk * KEYS_PER_WARP) * NHD;
    const float4* kb = (const float4*)(past_k + off);
    const float4* vb = (const float4*)(past_v + off);

    // ---- Phase 1: scores.  16 fully independent K loads. ----
    float s[NITER];
#pragma unroll
    for (int j = 0; j < NITER; ++j) {
        const float4 k4 = __ldcs(kb + j*32 + lane);
        float t = q4.x*k4.x + q4.y*k4.y + q4.z*k4.z + q4.w*k4.w;
        t += __shfl_xor_sync(0xffffffffu, t, 1);
        t += __shfl_xor_sync(0xffffffffu, t, 2);
        t += __shfl_xor_sync(0xffffffffu, t, 4);
        t += __shfl_xor_sync(0xffffffffu, t, 8);
        s[j] = t * 0.125f;                          // 1/sqrt(64)
    }

    // ---- Softmax over this lane's 16 scores. ----
    float m = s[0];
#pragma unroll
    for (int j = 1; j < NITER; ++j) m = fmaxf(m, s[j]);
    float l = 0.f;
#pragma unroll
    for (int j = 0; j < NITER; ++j) { s[j] = __expf(s[j] - m); l += s[j]; }

    // ---- Phase 2: weighted V accumulation.  16 independent V loads. ----
    float4 acc0 = make_float4(0.f,0.f,0.f,0.f);
    float4 acc1 = make_float4(0.f,0.f,0.f,0.f);
#pragma unroll
    for (int j = 0; j < NITER; j += 2) {
        const float4 va = __ldcs(vb + j*32 + lane);
        const float4 vc = __ldcs(vb + (j+1)*32 + lane);
        acc0.x += s[j]*va.x;   acc0.y += s[j]*va.y;
        acc0.z += s[j]*va.z;   acc0.w += s[j]*va.w;
        acc1.x += s[j+1]*vc.x; acc1.y += s[j+1]*vc.y;
        acc1.z += s[j+1]*vc.z; acc1.w += s[j+1]*vc.w;
    }
    float4 acc;
    acc.x = acc0.x + acc1.x; acc.y = acc0.y + acc1.y;
    acc.z = acc0.z + acc1.z; acc.w = acc0.w + acc1.w;

    // ---- Merge the two half-warp streams. ----
    const float mo = __shfl_xor_sync(0xffffffffu, m, 16);
    const float lo = __shfl_xor_sync(0xffffffffu, l, 16);
    float4 ao;
    ao.x = __shfl_xor_sync(0xffffffffu, acc.x, 16);
    ao.y = __shfl_xor_sync(0xffffffffu, acc.y, 16);
    ao.z = __shfl_xor_sync(0xffffffffu, acc.z, 16);
    ao.w = __shfl_xor_sync(0xffffffffu, acc.w, 16);
    const float M  = fmaxf(m, mo);
    const float wa = __expf(m - M), wb = __expf(mo - M);
    float4 comb;
    comb.x = acc.x*wa + ao.x*wb;
    comb.y = acc.y*wa + ao.y*wb;
    comb.z = acc.z*wa + ao.z*wb;
    comb.w = acc.w*wa + ao.w*wb;
    const float L = l*wa + lo*wb;

    if (lane < 16) ((float4*)sm_acc[warp])[l16] = comb;
    if (lane == 0) { sm_m[warp] = M; sm_l[warp] = L; }
    __syncthreads();

    if (threadIdx.x < NHD) {
        const int d = threadIdx.x;
        float Mb = sm_m[0];
#pragma unroll
        for (int w = 1; w < WARPS_PB; ++w) Mb = fmaxf(Mb, sm_m[w]);
        float Lb = 0.f, a = 0.f;
#pragma unroll
        for (int w = 0; w < WARPS_PB; ++w) {
            const float wg = __expf(sm_m[w] - Mb);
            a  += sm_acc[w][d] * wg;
            Lb += sm_l[w] * wg;
        }
        const int idx = bh*NCHUNK + blockIdx.x;
        g_acc[idx*NHD + d] = a;
        if (d == 0) { g_m[idx] = Mb; g_l[idx] = Lb; }
    }

    // ---- Release: publish this chunk to the side-stream reducer. ----
    __threadfence();
    __syncthreads();
    if (threadIdx.x == 0) atomicAdd(&g_cnt[bh], 1);
}

// ---------------------------------------------------------------------------
// Kernel C (side stream): FUSED per-bh reduce + output projection.
// grid NBH (128 blocks, <=1/SM -> all co-resident, deadlock-free), 256 thr.
//  1. Preload this block's 8 Wo rows at entry -> 4 MB of Wo DRAM latency is
//     hidden under the still-running scan.
//  2. Spin for this (b,h)'s 32 chunks, reduce, write ctx, bump g_ctxdone.
//  3. Spin for g_ctxdone==128, then output GEMV (8 rows x 8 batches) from
//     registers + L2-hot ctx.
// ---------------------------------------------------------------------------
__global__ void __launch_bounds__(256)
reduce_outproj_spin(const float* __restrict__ Wo,
                    const float* __restrict__ bo,
                    float* __restrict__ out) {
    const int bh  = blockIdx.x;
    const int tid = threadIdx.x;
    const int c = tid >> 6, d = tid & 63;
    const int b = bh >> 4, h = bh & 15;

    // ---- Preload 8 Wo rows (resolve during the scan / spin). ----
    float4 w[ROWS_PB];
#pragma unroll
    for (int j = 0; j < ROWS_PB; ++j)
        w[j] = ((const float4*)(Wo + (size_t)(bh*ROWS_PB + j) * ND))[tid];

    __shared__ float qs[NHD], ks[NHD];
    __shared__ float s_acc[4][NHD];
    __shared__ float s_l[4];
    __shared__ float s_dot;

    // RoPE q & k_new while waiting (independent of the scan's partials).
    if (tid < 32) {
        const int i = tid;
        const float inv = expf(-((float)(2*i) / (float)NHD) * LN10000);
        float sn, cs; sincosf((float)NPAST * inv, &sn, &cs);
        const float* gq = g_qkv + b*ND + h*NHD;
        const float* gk = g_qkv + NB*ND + b*ND + h*NHD;
        const float q1 = gq[i], q2 = gq[i+32];
        qs[i]    = q1*cs - q2*sn;
        qs[i+32] = q2*cs + q1*sn;
        const float k1 = gk[i], k2 = gk[i+32];
        ks[i]    = k1*cs - k2*sn;
        ks[i+32] = k2*cs + k1*sn;
    }
    __syncthreads();

    if (tid < 32) {
        float v = qs[tid]*ks[tid] + qs[tid+32]*ks[tid+32];
#pragma unroll
        for (int o = 16; o; o >>= 1) v += __shfl_xor_sync(0xffffffffu, v, o);
        if (tid == 0) s_dot = v * 0.125f;
    }

    // ---- Acquire: wait for all 32 chunks of this (b,h). ----
    if (tid == 0) {
        while (atomicAdd(&g_cnt[bh], 0) < NCHUNK) __nanosleep(128);
    }
    __syncthreads();
    __threadfence();

    const float* mptr = g_m + bh*NCHUNK;
    const float* lptr = g_l + bh*NCHUNK;
    const float* aptr = g_acc + (size_t)bh*NCHUNK*NHD;

    float M = -1e30f;
#pragma unroll
    for (int i = 0; i < NCHUNK; ++i) M = fmaxf(M, mptr[i]);

    float av[8], mv8[8], lv8[8];
#pragma unroll
    for (int j = 0; j < 8; ++j) {
        const int i = c + 4*j;
        av[j]  = aptr[i*NHD + d];
        mv8[j] = mptr[i];
        lv8[j] = lptr[i];
    }
    float a = 0.f, L = 0.f;
#pragma unroll
    for (int j = 0; j < 8; ++j) {
        const float wgt = __expf(mv8[j] - M);
        a += av[j] * wgt;
        L += lv8[j] * wgt;
    }
    s_acc[c][d] = a;
    if (d == 0) s_l[c] = L;
    __syncthreads();

    if (tid < NHD) {
        float A  = s_acc[0][tid] + s_acc[1][tid] + s_acc[2][tid] + s_acc[3][tid];
        float Lt = s_l[0] + s_l[1] + s_l[2] + s_l[3];
        const float s_new = s_dot;
        const float M2 = fmaxf(M, s_new);
        const float w0 = __expf(M - M2);
        const float p  = __expf(s_new - M2);
        const float vd = g_qkv[2*NB*ND + b*ND + h*NHD + tid];
        A  = A*w0 + p*vd;
        Lt = Lt*w0 + p;
        g_ctx[b*ND + h*NHD + tid] = A / Lt;
    }

    // ---- Release ctx; wait for all 128 ctx tiles. ----
    __threadfence();
    __syncthreads();
    if (tid == 0) {
        atomicAdd(&g_ctxdone, 1);
        while (atomicAdd(&g_ctxdone, 0) < NBH) __nanosleep(128);
    }
    __syncthreads();
    __threadfence();

    // ---- Output GEMV: 8 rows x 8 batches, ctx L2-hot, Wo in registers. ----
    float4 cv[NB];
#pragma unroll
    for (int bb = 0; bb < NB; ++bb)
        cv[bb] = ((const float4*)g_ctx)[bb*(ND/4) + tid];

    __shared__ float smo[8][NB+1];
    const int warp = tid >> 5, lane = tid & 31;
#pragma unroll
    for (int j = 0; j < ROWS_PB; ++j) {
        float acc[NB];
#pragma unroll
        for (int bb = 0; bb < NB; ++bb)
            acc[bb] = w[j].x*cv[bb].x + w[j].y*cv[bb].y + w[j].z*cv[bb].z + w[j].w*cv[bb].w;
#pragma unroll
        for (int bb = 0; bb < NB; ++bb) {
#pragma unroll
            for (int o = 16; o; o >>= 1) acc[bb] += __shfl_xor_sync(0xffffffffu, acc[bb], o);
        }
        if (lane == 0) {
#pragma unroll
            for (int bb = 0; bb < NB; ++bb) smo[warp][bb] = acc[bb];
        }
        __syncthreads();
        if (tid < NB) {
            float v = smo[0][tid];
#pragma unroll
            for (int ww = 1; ww < 8; ++ww) v += smo[ww][tid];
            const int row = bh*ROWS_PB + j;
            out[tid*ND + row] = v + bo[row];
        }
        __syncthreads();
    }
}

// ---------------------------------------------------------------------------
extern "C" void kernel_launch(void* const* d_in, const int* in_sizes, int n_in,
                              void* d_out, int out_size) {
    const float* x      = (const float*)d_in[0];
    const float* Wq     = (const float*)d_in[1];
    const float* bq     = (const float*)d_in[2];
    const float* Wk     = (const float*)d_in[3];
    const float* bk     = (const float*)d_in[4];
    const float* Wv     = (const float*)d_in[5];
    const float* bv     = (const float*)d_in[6];
    const float* Wo     = (const float*)d_in[7];
    const float* bo     = (const float*)d_in[8];
    const float* past_k = (const float*)d_in[9];
    const float* past_v = (const float*)d_in[10];
    float* out = (float*)d_out;

    static cudaStream_t s_side = nullptr;
    static cudaEvent_t  e_fork = nullptr, e_join = nullptr;
    if (s_side == nullptr) {
        cudaStreamCreateWithFlags(&s_side, cudaStreamNonBlocking);
        cudaEventCreateWithFlags(&e_fork, cudaEventDisableTiming);
        cudaEventCreateWithFlags(&e_join, cudaEventDisableTiming);
    }

    // proj_q also resets g_cnt/g_ctxdone; fork AFTER it so both streams see it.
    proj_q_kernel<<<ND, 256>>>(x, Wq, bq);
    cudaEventRecord(e_fork, 0);
    cudaStreamWaitEvent(s_side, e_fork, 0);

    attn_partial<<<dim3(NCHUNK, NBH), 256>>>(past_k, past_v);       // main
    proj_kv_kernel<<<2*ND, 256, 0, s_side>>>(x, Wk, bk, Wv, bv);    // side
    reduce_outproj_spin<<<NBH, 256, 0, s_side>>>(Wo, bo, out);      // side (writes out)

    // Join side stream back (capture legality + out completeness).
    cudaEventRecord(e_join, s_side);
    cudaStreamWaitEvent(0, e_join, 0);
}